// round 12
// baseline (speedup 1.0000x reference)
#include <cuda_runtime.h>
#include <cuda_bf16.h>
#include <cuda_fp16.h>
#include <cstdint>
#include <cstddef>
#include <math_constants.h>

#define NROWS     16384
#define NCODES    8192
#define DIM       256
#define ZQ_ELEMS  4194304
#define LOSS_OFF  4194304
#define CODES_OFF 4194305
#define CAND_WIN  4e-3f
#define MAXCAND   8
#define SPLITK    4
#define KCHUNK    2048

static __device__ float  g_logits[(size_t)NROWS * NCODES];                 // 512 MB
static __device__ __align__(16) __half g_w16[(size_t)NROWS * NCODES];      // 256 MB
static __device__ __align__(16) float  g_zqp[(size_t)SPLITK * ZQ_ELEMS];   // 67 MB
static __device__ __align__(16) __half g_z16[(size_t)NROWS * DIM];
static __device__ __align__(16) __half g_ch16[(size_t)NCODES * DIM];
static __device__ __align__(16) __half g_cl16[(size_t)NCODES * DIM];
static __device__ __align__(16) __half g_cth16[(size_t)DIM * NCODES];
static __device__ float  g_kl[NROWS];
static __device__ double g_part[4096];
static __device__ int    g_fixn;
static __device__ int    g_fixrows[NROWS];
static __device__ int    g_fixnc[NROWS];
static __device__ int    g_fixcand[NROWS][MAXCAND];

// ---------------- Threefry-2x32 (bit-exact JAX, key (0,42)) ----------------
// Inner log MUST be full logf (__logf abs-err near 1 corrupts top gumbels).
__device__ __forceinline__ float gumbel_at(uint32_t idx) {
  uint32_t x0 = 0u, x1 = idx;
  const uint32_t ks0 = 0u, ks1 = 42u, ks2 = 0x1BD11BDAu ^ ks0 ^ ks1;
  x0 += ks0; x1 += ks1;
#define TF_R(r) { x0 += x1; x1 = __funnelshift_l(x1, x1, (r)); x1 ^= x0; }
  TF_R(13) TF_R(15) TF_R(26) TF_R(6)  x0 += ks1; x1 += ks2 + 1u;
  TF_R(17) TF_R(29) TF_R(16) TF_R(24) x0 += ks2; x1 += ks0 + 2u;
  TF_R(13) TF_R(15) TF_R(26) TF_R(6)  x0 += ks0; x1 += ks1 + 3u;
  TF_R(17) TF_R(29) TF_R(16) TF_R(24) x0 += ks1; x1 += ks2 + 4u;
  TF_R(13) TF_R(15) TF_R(26) TF_R(6)  x0 += ks2; x1 += ks0 + 5u;
#undef TF_R
  uint32_t bits = x0 ^ x1;
  float f = __uint_as_float((bits >> 9) | 0x3f800000u) - 1.0f;
  float u = fmaxf(1.17549435e-38f, f + 1.17549435e-38f);
  return -__logf(-logf(u));
}

// ---------------- merged conversion (z + codebook + init) -------------------
__global__ __launch_bounds__(256) void conv_all_kernel(const float* __restrict__ z,
                                                       const float* __restrict__ cb)
{
  size_t i = (size_t)blockIdx.x * 256 + threadIdx.x;
  g_z16[i] = __float2half_rn(z[i]);
  if (i < (size_t)NCODES * DIM) {
    float v = cb[i];
    __half hi = __float2half_rn(v);
    g_ch16[i] = hi;
    g_cl16[i] = __float2half_rn(v - __half2float(hi));
    size_t row = i >> 8; int c = (int)(i & 255);
    g_cth16[(size_t)c * NCODES + row] = hi;
  }
  if (i == 0) g_fixn = 0;
}
__global__ void pad_kernel() {}

// ---------------- HMMA fp16 NT GEMM, 128x256x32, 512 thr, NPH phases --------
#define APITCH 80
#define A_BYTES 10240              /* 128 rows * 80 */
#define B_BYTES 20480              /* 256 rows * 80 */
#define STAGE_BYTES 30720
#define GEMM_SMEM (4 * STAGE_BYTES)   /* 122880 */

__device__ __forceinline__ uint32_t smem_u32(const void* p) {
  uint32_t a;
  asm("{ .reg .u64 t; cvta.to.shared.u64 t, %1; cvt.u32.u64 %0, t; }" : "=r"(a) : "l"(p));
  return a;
}
__device__ __forceinline__ void ldsm4(uint32_t a, uint32_t& r0, uint32_t& r1,
                                      uint32_t& r2, uint32_t& r3) {
  asm volatile("ldmatrix.sync.aligned.m8n8.x4.shared.b16 {%0,%1,%2,%3}, [%4];"
               : "=r"(r0), "=r"(r1), "=r"(r2), "=r"(r3) : "r"(a));
}
__device__ __forceinline__ void mma16816(float* d, const uint32_t* a,
                                         uint32_t b0, uint32_t b1) {
  asm volatile("mma.sync.aligned.m16n8k16.row.col.f32.f16.f16.f32 "
               "{%0,%1,%2,%3}, {%4,%5,%6,%7}, {%8,%9}, {%0,%1,%2,%3};"
               : "+f"(d[0]), "+f"(d[1]), "+f"(d[2]), "+f"(d[3])
               : "r"(a[0]), "r"(a[1]), "r"(a[2]), "r"(a[3]), "r"(b0), "r"(b1));
}

__device__ __forceinline__ void load_stage(uint32_t sbase,
    const uint16_t* __restrict__ A, const uint16_t* __restrict__ B,
    size_t bm, size_t bn, int k0, int Kstride, int t)
{
  {
    int r = t >> 2, c = t & 3;                    // A: 512 loads
    uint32_t da = sbase + (uint32_t)(r * APITCH + c * 16);
    const void* sa = A + (bm + (size_t)r) * (size_t)Kstride + k0 + c * 8;
    asm volatile("cp.async.cg.shared.global [%0], [%1], 16;" :: "r"(da), "l"(sa));
  }
#pragma unroll
  for (int j = 0; j < 2; ++j) {                   // B: 1024 loads
    int idx = t + j * 512;
    int r = idx >> 2, c = idx & 3;
    uint32_t db = sbase + A_BYTES + (uint32_t)(r * APITCH + c * 16);
    const void* sb = B + (bn + (size_t)r) * (size_t)Kstride + k0 + c * 8;
    asm volatile("cp.async.cg.shared.global [%0], [%1], 16;" :: "r"(db), "l"(sb));
  }
  asm volatile("cp.async.commit_group;");
}

template<int NPH>
__device__ __forceinline__ void load_gk(int g, int KTp, int koff, uint32_t sb0,
    const uint16_t* A0, const uint16_t* B0, const uint16_t* B1,
    size_t bm, size_t bn, int Kstride, int t)
{
  int ph = (NPH == 1) ? 0 : (g / KTp);
  int k0 = koff + ((NPH == 1) ? g : (g - ph * KTp)) * 32;
  const uint16_t* Bp = (ph == 0) ? B0 : B1;
  load_stage(sb0 + (uint32_t)((g & 3) * STAGE_BYTES), A0, Bp, bm, bn, k0, Kstride, t);
}

template<int NPH>
__global__ __launch_bounds__(512, 1) void gemm_hmma_kernel(
    const uint16_t* __restrict__ A0,
    const uint16_t* __restrict__ B0, const uint16_t* __restrict__ B1,
    float* __restrict__ C, int Ntot, int Kp, int Kstride, size_t zstride)
{
  extern __shared__ char smem[];
  const uint32_t sb0 = smem_u32(smem);
  const int t = threadIdx.x;
  const int wid = t >> 5, lane = t & 31;
  const int wm = wid >> 2, wn = wid & 3;          // 4x4 warp grid, warp tile 32x64
  const size_t bm = (size_t)blockIdx.y * 128;
  const size_t bn = (size_t)blockIdx.x * 256;
  const int koff = blockIdx.z * Kp;
  C += (size_t)blockIdx.z * zstride;
  const int KTp = Kp >> 5;
  const int KTtot = KTp * NPH;

  float acc[2][8][4];
#pragma unroll
  for (int mi = 0; mi < 2; ++mi)
#pragma unroll
    for (int ni = 0; ni < 8; ++ni)
#pragma unroll
      for (int q = 0; q < 4; ++q) acc[mi][ni][q] = 0.0f;

  load_gk<NPH>(0, KTp, koff, sb0, A0, B0, B1, bm, bn, Kstride, t);
  load_gk<NPH>(1, KTp, koff, sb0, A0, B0, B1, bm, bn, Kstride, t);
  load_gk<NPH>(2, KTp, koff, sb0, A0, B0, B1, bm, bn, Kstride, t);

  const uint32_t aoff = (uint32_t)((wm * 32 + (lane & 15)) * APITCH + (lane >> 4) * 16);
  const uint32_t boff = A_BYTES + (uint32_t)((wn * 64 + (lane & 15)) * APITCH + (lane >> 4) * 16);

  // single-barrier multistage (see R10 proof); stage ring of 4, prefetch dist 3
  for (int k = 0; k < KTtot; ++k) {
    asm volatile("cp.async.wait_group 2;");
    __syncthreads();
    if (k + 3 < KTtot)
      load_gk<NPH>(k + 3, KTp, koff, sb0, A0, B0, B1, bm, bn, Kstride, t);
    else
      asm volatile("cp.async.commit_group;");

    const uint32_t sbase = sb0 + (uint32_t)((k & 3) * STAGE_BYTES);
#pragma unroll
    for (int kk = 0; kk < 2; ++kk) {
      uint32_t a0[4], a1[4];
      ldsm4(sbase + aoff + kk * 32,               a0[0], a0[1], a0[2], a0[3]);
      ldsm4(sbase + aoff + 16 * APITCH + kk * 32, a1[0], a1[1], a1[2], a1[3]);
      uint32_t bfr[8][2];
#pragma unroll
      for (int nj = 0; nj < 4; ++nj) {
        uint32_t r0, r1, r2, r3;
        ldsm4(sbase + boff + nj * 16 * APITCH + kk * 32, r0, r1, r2, r3);
        bfr[2 * nj + 0][0] = r0; bfr[2 * nj + 0][1] = r2;
        bfr[2 * nj + 1][0] = r1; bfr[2 * nj + 1][1] = r3;
      }
#pragma unroll
      for (int ni = 0; ni < 8; ++ni) {
        mma16816(acc[0][ni], a0, bfr[ni][0], bfr[ni][1]);
        mma16816(acc[1][ni], a1, bfr[ni][0], bfr[ni][1]);
      }
    }
  }
  __syncthreads();

  // epilogue: two 128x128 halves staged through smem, coalesced fp32 stores
  const int r4 = lane >> 2;
  const int c4 = (lane & 3) * 2;
  float* sC = (float*)smem;
#pragma unroll
  for (int h = 0; h < 2; ++h) {
    if ((wn >> 1) == h) {
#pragma unroll
      for (int mi = 0; mi < 2; ++mi)
#pragma unroll
        for (int ni = 0; ni < 8; ++ni) {
          int row = wm * 32 + mi * 16 + r4;
          int col = (wn & 1) * 64 + ni * 8 + c4;
          sC[(size_t)row * 132 + col]     = acc[mi][ni][0];
          sC[(size_t)row * 132 + col + 1] = acc[mi][ni][1];
          sC[(size_t)(row + 8) * 132 + col]     = acc[mi][ni][2];
          sC[(size_t)(row + 8) * 132 + col + 1] = acc[mi][ni][3];
        }
    }
    __syncthreads();
#pragma unroll
    for (int j = 0; j < 8; ++j) {
      int idx = t + j * 512;
      int r = idx >> 5, ch = idx & 31;
      float4 v = ((const float4*)sC)[r * 33 + ch];
      *(float4*)(C + (bm + (size_t)r) * (size_t)Ntot + bn + h * 128 + ch * 4) = v;
    }
    __syncthreads();
  }
}

// ---------------- deterministic split-K reduce + straight-through + commit --
__global__ __launch_bounds__(256) void zq_reduce_kernel(const float* __restrict__ z,
                                                        float* __restrict__ out)
{
  __shared__ double red[256];
  const int t = threadIdx.x;
  const size_t i4 = ((size_t)blockIdx.x * 256 + t) * 4;
  float4 a = *(const float4*)(g_zqp + i4);
#pragma unroll
  for (int c = 1; c < SPLITK; ++c) {
    float4 b = *(const float4*)(g_zqp + (size_t)c * ZQ_ELEMS + i4);
    a.x += b.x; a.y += b.y; a.z += b.z; a.w += b.w;
  }
  float4 zv = *(const float4*)(z + i4);
  float d0 = a.x - zv.x, d1 = a.y - zv.y, d2 = a.z - zv.z, d3 = a.w - zv.w;
  *(float4*)(out + i4) = make_float4(zv.x + d0, zv.y + d1, zv.z + d2, zv.w + d3);
  red[t] = (double)(d0 * d0) + (double)(d1 * d1) +
           (double)(d2 * d2) + (double)(d3 * d3);
  __syncthreads();
  for (int s = 128; s > 0; s >>= 1) { if (t < s) red[t] += red[t + s]; __syncthreads(); }
  if (t == 0) g_part[blockIdx.x] = red[0];
}

// ---------------- per-row pass (2 exps/elem, analytic KL) -------------------
__global__ __launch_bounds__(256) void row_kernel(float* __restrict__ out)
{
  __shared__ float s_m1[8], s_m2[8], s_my[8], s_z1[8], s_z2[8], s_ql[8];
  __shared__ int   s_i1[8];
  __shared__ int   scount;
  __shared__ int   cands[MAXCAND];
  const int row = blockIdx.x, t = threadIdx.x;
  const int w = t >> 5, lane = t & 31;
  const float* __restrict__ lrow = g_logits + (size_t)row * NCODES + t * 32;
  const uint32_t base = (uint32_t)row * (uint32_t)NCODES + (uint32_t)(t * 32);

  float lv[32], yv[32];
#pragma unroll
  for (int j = 0; j < 8; ++j) *(float4*)(lv + j * 4) = ((const float4*)lrow)[j];

  if (t == 0) scount = 0;
  float m1 = -CUDART_INF_F, m2 = -CUDART_INF_F, my = -CUDART_INF_F;
  int i1 = 0;
#pragma unroll
  for (int i = 0; i < 32; ++i) {
    float l = lv[i];
    float y = l + gumbel_at(base + (uint32_t)i);
    yv[i] = y;
    if (l > m1) { m2 = m1; m1 = l; i1 = t * 32 + i; }
    else if (l > m2) m2 = l;
    my = fmaxf(my, y);
  }
#pragma unroll
  for (int o = 16; o > 0; o >>= 1) {
    float b1 = __shfl_xor_sync(0xFFFFFFFFu, m1, o);
    int   bi = __shfl_xor_sync(0xFFFFFFFFu, i1, o);
    float b2 = __shfl_xor_sync(0xFFFFFFFFu, m2, o);
    my = fmaxf(my, __shfl_xor_sync(0xFFFFFFFFu, my, o));
    if (b1 > m1)      { m2 = fmaxf(m1, b2); m1 = b1; i1 = bi; }
    else if (b1 < m1) { m2 = fmaxf(m2, b1); }
    else              { i1 = (bi < i1) ? bi : i1; m2 = m1; }
  }
  if (lane == 0) { s_m1[w] = m1; s_i1[w] = i1; s_m2[w] = m2; s_my[w] = my; }
  __syncthreads();
  float M1 = -CUDART_INF_F, M2nd = -CUDART_INF_F, MY = -CUDART_INF_F;
  int AM = 0;
#pragma unroll
  for (int j = 0; j < 8; ++j) {
    float b1 = s_m1[j]; int bi = s_i1[j]; float b2 = s_m2[j];
    MY = fmaxf(MY, s_my[j]);
    if (b1 > M1)      { M2nd = fmaxf(M1, b2); M1 = b1; AM = bi; }
    else if (b1 < M1) { M2nd = fmaxf(M2nd, b1); }
    else              { AM = (bi < AM) ? bi : AM; M2nd = M1; }
  }

  if (M1 - M2nd < CAND_WIN) {
    const float thr = M1 - CAND_WIN;
#pragma unroll
    for (int i = 0; i < 32; ++i) {
      if (lv[i] >= thr) {
        int p = atomicAdd(&scount, 1);
        if (p < MAXCAND) cands[p] = t * 32 + i;
      }
    }
  }

  // single exp pass: e1 (softmax of l), e2 (softmax of y); e2 kept in yv
  float z1 = 0.0f, z2 = 0.0f, ql = 0.0f;
#pragma unroll
  for (int i = 0; i < 32; ++i) {
    float e1 = __expf(lv[i] - M1);
    float e2 = __expf(yv[i] - MY);
    z1 += e1; z2 += e2; ql = fmaf(e1, lv[i], ql);
    yv[i] = e2;
  }
#pragma unroll
  for (int o = 16; o > 0; o >>= 1) {
    z1 += __shfl_xor_sync(0xFFFFFFFFu, z1, o);
    z2 += __shfl_xor_sync(0xFFFFFFFFu, z2, o);
    ql += __shfl_xor_sync(0xFFFFFFFFu, ql, o);
  }
  if (lane == 0) { s_z1[w] = z1; s_z2[w] = z2; s_ql[w] = ql; }
  __syncthreads();
  float Z1 = 0.0f, Z2 = 0.0f, QL = 0.0f;
#pragma unroll
  for (int j = 0; j < 8; ++j) { Z1 += s_z1[j]; Z2 += s_z2[j]; QL += s_ql[j]; }
  const float rZ2 = 1.0f / Z2;

  __half w16[32];
#pragma unroll
  for (int i = 0; i < 32; ++i) w16[i] = __float2half_rn(yv[i] * rZ2);
  {
    __half* wp = g_w16 + (size_t)row * NCODES + t * 32;
#pragma unroll
    for (int j = 0; j < 4; ++j) ((uint4*)wp)[j] = ((const uint4*)w16)[j];
  }
  if (t == 0) {
    // kl = sum q*(l - M1 - lZ1 + ln 8192); q*8192 >> 1e-10 always here
    float lZ1 = logf(Z1);
    g_kl[row] = QL / Z1 - M1 - lZ1 + 9.0109131f;
    out[CODES_OFF + row] = (float)AM;
    if (scount > 1) {
      int j = atomicAdd(&g_fixn, 1);
      g_fixrows[j] = row;
      int nc = (scount <= MAXCAND) ? scount : 0;
      g_fixnc[j] = nc;
      for (int q = 0; q < nc; ++q) g_fixcand[j][q] = cands[q];
    }
  }
}

// ---------------- exact fp32 rescore (candidates, fallback full) ------------
__global__ __launch_bounds__(256) void fixup_kernel(const float* __restrict__ z,
                                                    const float* __restrict__ cb,
                                                    float* __restrict__ out)
{
  __shared__ float zs[256];
  __shared__ float scr[MAXCAND];
  __shared__ float rv[256];
  __shared__ int   ri[256];
  const int t = threadIdx.x, w = t >> 5, lane = t & 31;
  const int nfix = g_fixn;

  for (int e = blockIdx.x; e < nfix; e += gridDim.x) {
    const int row = g_fixrows[e];
    const int nc  = g_fixnc[e];
    zs[t] = z[(size_t)row * DIM + t];
    __syncthreads();

    if (nc > 0) {
      if (w < nc) {
        int code = g_fixcand[e][w];
        const float* cp = cb + (size_t)code * DIM + lane * 8;
        float s = 0.0f;
#pragma unroll
        for (int u = 0; u < 8; ++u) s = fmaf(zs[lane * 8 + u], cp[u], s);
#pragma unroll
        for (int o = 16; o > 0; o >>= 1) s += __shfl_xor_sync(0xFFFFFFFFu, s, o);
        if (lane == 0) scr[w] = s;
      }
      __syncthreads();
      if (t == 0) {
        float best = -CUDART_INF_F; int bi = 0x7FFFFFFF;
        for (int ci = 0; ci < nc; ++ci) {
          int code = g_fixcand[e][ci];
          float s = scr[ci];
          if (s > best || (s == best && code < bi)) { best = s; bi = code; }
        }
        out[CODES_OFF + row] = (float)bi;
      }
    } else {
      float best = -CUDART_INF_F; int bi = 0;
      for (int c = t; c < NCODES; c += 256) {
        const float* cp = cb + (size_t)c * DIM;
        float s0 = 0.f, s1 = 0.f, s2 = 0.f, s3 = 0.f;
#pragma unroll 8
        for (int k = 0; k < DIM; k += 4) {
          s0 = fmaf(zs[k],     cp[k],     s0);
          s1 = fmaf(zs[k + 1], cp[k + 1], s1);
          s2 = fmaf(zs[k + 2], cp[k + 2], s2);
          s3 = fmaf(zs[k + 3], cp[k + 3], s3);
        }
        float s = (s0 + s1) + (s2 + s3);
        if (s > best) { best = s; bi = c; }
      }
      rv[t] = best; ri[t] = bi;
      __syncthreads();
      for (int s = 128; s > 0; s >>= 1) {
        if (t < s) {
          float v = rv[t + s]; int vi = ri[t + s];
          if (v > rv[t] || (v == rv[t] && vi < ri[t])) { rv[t] = v; ri[t] = vi; }
        }
        __syncthreads();
      }
      if (t == 0) out[CODES_OFF + row] = (float)ri[0];
    }
    __syncthreads();
  }
}

// ---------------- finalize losses ------------------------------------------
__global__ __launch_bounds__(256) void finalize_kernel(float* __restrict__ out)
{
  __shared__ double red[256];
  const int t = threadIdx.x;
  double cs = 0.0;
  for (int i = t; i < 4096; i += 256) cs += g_part[i];
  red[t] = cs;
  __syncthreads();
  for (int s = 128; s > 0; s >>= 1) { if (t < s) red[t] += red[t + s]; __syncthreads(); }
  const double commit_sum = red[0];
  __syncthreads();
  double ks = 0.0;
  for (int i = t; i < NROWS; i += 256) ks += (double)g_kl[i];
  red[t] = ks;
  __syncthreads();
  for (int s = 128; s > 0; s >>= 1) { if (t < s) red[t] += red[t + s]; __syncthreads(); }
  if (t == 0) {
    float commit = 0.25f * (float)(commit_sum / (double)ZQ_ELEMS);
    float klm    = 0.01f * (float)(red[0] / (double)NROWS);
    out[LOSS_OFF] = commit + klm;
  }
}

// ---------------- launch ----------------------------------------------------
extern "C" void kernel_launch(void* const* d_in, const int* in_sizes, int n_in,
                              void* d_out, int out_size)
{
  const float* z  = (const float*)d_in[0];
  const float* cb = (const float*)d_in[1];
  float* out = (float*)d_out;

  void *pl, *pw, *pz16, *pch, *pcl, *pcth, *pzqp;
  cudaGetSymbolAddress(&pl, g_logits);
  cudaGetSymbolAddress(&pw, g_w16);
  cudaGetSymbolAddress(&pz16, g_z16);
  cudaGetSymbolAddress(&pch, g_ch16);
  cudaGetSymbolAddress(&pcl, g_cl16);
  cudaGetSymbolAddress(&pcth, g_cth16);
  cudaGetSymbolAddress(&pzqp, g_zqp);

  cudaFuncSetAttribute(gemm_hmma_kernel<2>,
                       cudaFuncAttributeMaxDynamicSharedMemorySize, GEMM_SMEM);
  cudaFuncSetAttribute(gemm_hmma_kernel<1>,
                       cudaFuncAttributeMaxDynamicSharedMemorySize, GEMM_SMEM);

  conv_all_kernel<<<ZQ_ELEMS / 256, 256>>>(z, cb);      // 1
  pad_kernel<<<1, 32>>>();                              // 2
  pad_kernel<<<1, 32>>>();                              // 3

  // 4 (ncu slot): GEMM1 logits = z16*ch16 + z16*cl16, fp16 2-phase, 128x256 tile
  dim3 g1(NCODES / 256, NROWS / 128, 1);
  gemm_hmma_kernel<2><<<g1, 512, GEMM_SMEM>>>(
      (const uint16_t*)pz16,
      (const uint16_t*)pch, (const uint16_t*)pcl,
      (float*)pl, NCODES, DIM, DIM, 0);

  row_kernel<<<NROWS, 256>>>(out);                      // 5

  // 6: GEMM2 split-K(4): zq_part[c] = w16 @ cth16 over K-chunk c
  dim3 g2(DIM / 256, NROWS / 128, SPLITK);
  gemm_hmma_kernel<1><<<g2, 512, GEMM_SMEM>>>(
      (const uint16_t*)pw,
      (const uint16_t*)pcth, (const uint16_t*)pcth,
      (float*)pzqp, DIM, KCHUNK, NCODES, (size_t)ZQ_ELEMS);

  zq_reduce_kernel<<<ZQ_ELEMS / 1024, 256>>>(z, out);   // 7
  fixup_kernel<<<128, 256>>>(z, cb, out);               // 8
  finalize_kernel<<<1, 256>>>(out);                     // 9
}

// round 14
// speedup vs baseline: 1.0603x; 1.0603x over previous
#include <cuda_runtime.h>
#include <cuda_bf16.h>
#include <cuda_fp16.h>
#include <cstdint>
#include <cstddef>
#include <math_constants.h>

#define NROWS     16384
#define NCODES    8192
#define DIM       256
#define ZQ_ELEMS  4194304
#define LOSS_OFF  4194304
#define CODES_OFF 4194305
#define CAND_WIN  4e-3f
#define MAXCAND   8
#define SPLITK    4
#define KCHUNK    2048

static __device__ float  g_logits[(size_t)NROWS * NCODES];
static __device__ __align__(16) __half g_w16[(size_t)NROWS * NCODES];
static __device__ __align__(16) float  g_zqp[(size_t)SPLITK * ZQ_ELEMS];
static __device__ __align__(16) __half g_z16[(size_t)NROWS * DIM];
static __device__ __align__(16) __half g_ch16[(size_t)NCODES * DIM];
static __device__ __align__(16) __half g_cl16[(size_t)NCODES * DIM];
static __device__ __align__(16) __half g_cth16[(size_t)DIM * NCODES];
static __device__ float  g_kl[NROWS];
static __device__ double g_part[4096];
static __device__ int    g_fixn;
static __device__ int    g_fixrows[NROWS];
static __device__ int    g_fixnc[NROWS];
static __device__ int    g_fixcand[NROWS][MAXCAND];

// ---------------- Threefry-2x32 (bit-exact JAX, key (0,42)) ----------------
// Inner log MUST be full logf (__logf abs-err near 1 corrupts top gumbels).
__device__ __forceinline__ float gumbel_at(uint32_t idx) {
  uint32_t x0 = 0u, x1 = idx;
  const uint32_t ks0 = 0u, ks1 = 42u, ks2 = 0x1BD11BDAu ^ ks0 ^ ks1;
  x0 += ks0; x1 += ks1;
#define TF_R(r) { x0 += x1; x1 = __funnelshift_l(x1, x1, (r)); x1 ^= x0; }
  TF_R(13) TF_R(15) TF_R(26) TF_R(6)  x0 += ks1; x1 += ks2 + 1u;
  TF_R(17) TF_R(29) TF_R(16) TF_R(24) x0 += ks2; x1 += ks0 + 2u;
  TF_R(13) TF_R(15) TF_R(26) TF_R(6)  x0 += ks0; x1 += ks1 + 3u;
  TF_R(17) TF_R(29) TF_R(16) TF_R(24) x0 += ks1; x1 += ks2 + 4u;
  TF_R(13) TF_R(15) TF_R(26) TF_R(6)  x0 += ks2; x1 += ks0 + 5u;
#undef TF_R
  uint32_t bits = x0 ^ x1;
  float f = __uint_as_float((bits >> 9) | 0x3f800000u) - 1.0f;
  float u = fmaxf(1.17549435e-38f, f + 1.17549435e-38f);
  return -__logf(-logf(u));
}

// ---------------- merged conversion (z + codebook + init) -------------------
__global__ __launch_bounds__(256) void conv_all_kernel(const float* __restrict__ z,
                                                       const float* __restrict__ cb)
{
  size_t i = (size_t)blockIdx.x * 256 + threadIdx.x;
  g_z16[i] = __float2half_rn(z[i]);
  if (i < (size_t)NCODES * DIM) {
    float v = cb[i];
    __half hi = __float2half_rn(v);
    g_ch16[i] = hi;
    g_cl16[i] = __float2half_rn(v - __half2float(hi));
    size_t row = i >> 8; int c = (int)(i & 255);
    g_cth16[(size_t)c * NCODES + row] = hi;
  }
  if (i == 0) g_fixn = 0;
}
__global__ void pad_kernel() {}

// ---------------- HMMA fp16 NT GEMM, 128x128x32 @256thr, 2 CTA/SM -----------
#define APITCH 80
#define STAGE_BYTES 20480
#define GEMM_SMEM (4 * STAGE_BYTES)

__device__ __forceinline__ uint32_t smem_u32(const void* p) {
  uint32_t a;
  asm("{ .reg .u64 t; cvta.to.shared.u64 t, %1; cvt.u32.u64 %0, t; }" : "=r"(a) : "l"(p));
  return a;
}
__device__ __forceinline__ void ldsm4(uint32_t a, uint32_t& r0, uint32_t& r1,
                                      uint32_t& r2, uint32_t& r3) {
  asm volatile("ldmatrix.sync.aligned.m8n8.x4.shared.b16 {%0,%1,%2,%3}, [%4];"
               : "=r"(r0), "=r"(r1), "=r"(r2), "=r"(r3) : "r"(a));
}
__device__ __forceinline__ void mma16816(float* d, const uint32_t* a,
                                         uint32_t b0, uint32_t b1) {
  asm volatile("mma.sync.aligned.m16n8k16.row.col.f32.f16.f16.f32 "
               "{%0,%1,%2,%3}, {%4,%5,%6,%7}, {%8,%9}, {%0,%1,%2,%3};"
               : "+f"(d[0]), "+f"(d[1]), "+f"(d[2]), "+f"(d[3])
               : "r"(a[0]), "r"(a[1]), "r"(a[2]), "r"(a[3]), "r"(b0), "r"(b1));
}

__device__ __forceinline__ void load_stage(uint32_t sbase,
    const uint16_t* __restrict__ A, const uint16_t* __restrict__ B,
    size_t bm, size_t bn, int k0, int Kstride, int t)
{
#pragma unroll
  for (int j = 0; j < 2; ++j) {
    int idx = t + j * 256;
    int r = idx >> 2, c = idx & 3;
    uint32_t da = sbase + (uint32_t)(r * APITCH + c * 16);
    const void* sa = A + (bm + (size_t)r) * (size_t)Kstride + k0 + c * 8;
    asm volatile("cp.async.cg.shared.global [%0], [%1], 16;" :: "r"(da), "l"(sa));
    uint32_t db = sbase + 10240 + (uint32_t)(r * APITCH + c * 16);
    const void* sb = B + (bn + (size_t)r) * (size_t)Kstride + k0 + c * 8;
    asm volatile("cp.async.cg.shared.global [%0], [%1], 16;" :: "r"(db), "l"(sb));
  }
  asm volatile("cp.async.commit_group;");
}

template<int NPH>
__device__ __forceinline__ void load_gk(int g, int KTp, int koff, uint32_t sb0,
    const uint16_t* A0, const uint16_t* B0, const uint16_t* B1,
    size_t bm, size_t bn, int Kstride, int t)
{
  int ph = (NPH == 1) ? 0 : (g / KTp);
  int k0 = koff + ((NPH == 1) ? g : (g - ph * KTp)) * 32;
  const uint16_t* Bp = (ph == 0) ? B0 : B1;
  load_stage(sb0 + (uint32_t)((g & 3) * STAGE_BYTES), A0, Bp, bm, bn, k0, Kstride, t);
}

template<int NPH>
__global__ __launch_bounds__(256, 2) void gemm_hmma_kernel(
    const uint16_t* __restrict__ A0,
    const uint16_t* __restrict__ B0, const uint16_t* __restrict__ B1,
    float* __restrict__ C, int Ntot, int Kp, int Kstride, size_t zstride)
{
  extern __shared__ char smem[];
  const uint32_t sb0 = smem_u32(smem);
  const int t = threadIdx.x;
  const int wid = t >> 5, lane = t & 31;
  const int wm = wid >> 1, wn = wid & 1;          // 4x2 warp grid, warp tile 32x64
  const size_t bm = (size_t)blockIdx.y * 128;
  const size_t bn = (size_t)blockIdx.x * 128;
  const int koff = blockIdx.z * Kp;
  C += (size_t)blockIdx.z * zstride;
  const int KTp = Kp >> 5;
  const int KTtot = KTp * NPH;

  float acc[2][8][4];
#pragma unroll
  for (int mi = 0; mi < 2; ++mi)
#pragma unroll
    for (int ni = 0; ni < 8; ++ni)
#pragma unroll
      for (int q = 0; q < 4; ++q) acc[mi][ni][q] = 0.0f;

  load_gk<NPH>(0, KTp, koff, sb0, A0, B0, B1, bm, bn, Kstride, t);
  load_gk<NPH>(1, KTp, koff, sb0, A0, B0, B1, bm, bn, Kstride, t);
  load_gk<NPH>(2, KTp, koff, sb0, A0, B0, B1, bm, bn, Kstride, t);

  const uint32_t aoff = (uint32_t)((wm * 32 + (lane & 15)) * APITCH + (lane >> 4) * 16);
  const uint32_t boff = 10240u + (uint32_t)((wn * 64 + (lane & 15)) * APITCH + (lane >> 4) * 16);

  // single-barrier multistage (R10 proof): ring of 4, prefetch distance 3
  for (int k = 0; k < KTtot; ++k) {
    asm volatile("cp.async.wait_group 2;");
    __syncthreads();
    if (k + 3 < KTtot)
      load_gk<NPH>(k + 3, KTp, koff, sb0, A0, B0, B1, bm, bn, Kstride, t);
    else
      asm volatile("cp.async.commit_group;");

    const uint32_t sbase = sb0 + (uint32_t)((k & 3) * STAGE_BYTES);
#pragma unroll
    for (int kk = 0; kk < 2; ++kk) {
      uint32_t a0[4], a1[4];
      ldsm4(sbase + aoff + kk * 32,               a0[0], a0[1], a0[2], a0[3]);
      ldsm4(sbase + aoff + 16 * APITCH + kk * 32, a1[0], a1[1], a1[2], a1[3]);
      uint32_t bfr[8][2];
#pragma unroll
      for (int nj = 0; nj < 4; ++nj) {
        uint32_t r0, r1, r2, r3;
        ldsm4(sbase + boff + nj * 16 * APITCH + kk * 32, r0, r1, r2, r3);
        bfr[2 * nj + 0][0] = r0; bfr[2 * nj + 0][1] = r2;
        bfr[2 * nj + 1][0] = r1; bfr[2 * nj + 1][1] = r3;
      }
#pragma unroll
      for (int ni = 0; ni < 8; ++ni) {
        mma16816(acc[0][ni], a0, bfr[ni][0], bfr[ni][1]);
        mma16816(acc[1][ni], a1, bfr[ni][0], bfr[ni][1]);
      }
    }
  }
  __syncthreads();

  const int r4 = lane >> 2;
  const int c4 = (lane & 3) * 2;
  float* sC = (float*)smem;
#pragma unroll
  for (int mi = 0; mi < 2; ++mi)
#pragma unroll
    for (int ni = 0; ni < 8; ++ni) {
      int row = wm * 32 + mi * 16 + r4;
      int col = wn * 64 + ni * 8 + c4;
      sC[(size_t)row * 132 + col]     = acc[mi][ni][0];
      sC[(size_t)row * 132 + col + 1] = acc[mi][ni][1];
      sC[(size_t)(row + 8) * 132 + col]     = acc[mi][ni][2];
      sC[(size_t)(row + 8) * 132 + col + 1] = acc[mi][ni][3];
    }
  __syncthreads();
#pragma unroll
  for (int j = 0; j < 16; ++j) {
    int idx = t + j * 256;
    int r = idx >> 5, ch = idx & 31;
    float4 v = ((const float4*)sC)[r * 33 + ch];
    *(float4*)(C + (bm + (size_t)r) * (size_t)Ntot + bn + ch * 4) = v;
  }
}

// ---------------- deterministic split-K reduce + straight-through + commit --
__global__ __launch_bounds__(256) void zq_reduce_kernel(const float* __restrict__ z,
                                                        float* __restrict__ out)
{
  __shared__ double red[256];
  const int t = threadIdx.x;
  const size_t i4 = ((size_t)blockIdx.x * 256 + t) * 4;
  float4 a = *(const float4*)(g_zqp + i4);
#pragma unroll
  for (int c = 1; c < SPLITK; ++c) {
    float4 b = *(const float4*)(g_zqp + (size_t)c * ZQ_ELEMS + i4);
    a.x += b.x; a.y += b.y; a.z += b.z; a.w += b.w;
  }
  float4 zv = *(const float4*)(z + i4);
  float d0 = a.x - zv.x, d1 = a.y - zv.y, d2 = a.z - zv.z, d3 = a.w - zv.w;
  *(float4*)(out + i4) = make_float4(zv.x + d0, zv.y + d1, zv.z + d2, zv.w + d3);
  red[t] = (double)(d0 * d0) + (double)(d1 * d1) +
           (double)(d2 * d2) + (double)(d3 * d3);
  __syncthreads();
  for (int s = 128; s > 0; s >>= 1) { if (t < s) red[t] += red[t + s]; __syncthreads(); }
  if (t == 0) g_part[blockIdx.x] = red[0];
}

// ---------------- per-row pass (2 exps/elem, analytic KL) -------------------
__global__ __launch_bounds__(256) void row_kernel(float* __restrict__ out)
{
  __shared__ float s_m1[8], s_m2[8], s_my[8], s_z1[8], s_z2[8], s_ql[8];
  __shared__ int   s_i1[8];
  __shared__ int   scount;
  __shared__ int   cands[MAXCAND];
  const int row = blockIdx.x, t = threadIdx.x;
  const int w = t >> 5, lane = t & 31;
  const float* __restrict__ lrow = g_logits + (size_t)row * NCODES + t * 32;
  const uint32_t base = (uint32_t)row * (uint32_t)NCODES + (uint32_t)(t * 32);

  float lv[32], yv[32];
#pragma unroll
  for (int j = 0; j < 8; ++j) *(float4*)(lv + j * 4) = ((const float4*)lrow)[j];

  if (t == 0) scount = 0;
  float m1 = -CUDART_INF_F, m2 = -CUDART_INF_F, my = -CUDART_INF_F;
  int i1 = 0;
#pragma unroll
  for (int i = 0; i < 32; ++i) {
    float l = lv[i];
    float y = l + gumbel_at(base + (uint32_t)i);
    yv[i] = y;
    if (l > m1) { m2 = m1; m1 = l; i1 = t * 32 + i; }
    else if (l > m2) m2 = l;
    my = fmaxf(my, y);
  }
#pragma unroll
  for (int o = 16; o > 0; o >>= 1) {
    float b1 = __shfl_xor_sync(0xFFFFFFFFu, m1, o);
    int   bi = __shfl_xor_sync(0xFFFFFFFFu, i1, o);
    float b2 = __shfl_xor_sync(0xFFFFFFFFu, m2, o);
    my = fmaxf(my, __shfl_xor_sync(0xFFFFFFFFu, my, o));
    if (b1 > m1)      { m2 = fmaxf(m1, b2); m1 = b1; i1 = bi; }
    else if (b1 < m1) { m2 = fmaxf(m2, b1); }
    else              { i1 = (bi < i1) ? bi : i1; m2 = m1; }
  }
  if (lane == 0) { s_m1[w] = m1; s_i1[w] = i1; s_m2[w] = m2; s_my[w] = my; }
  __syncthreads();
  float M1 = -CUDART_INF_F, M2nd = -CUDART_INF_F, MY = -CUDART_INF_F;
  int AM = 0;
#pragma unroll
  for (int j = 0; j < 8; ++j) {
    float b1 = s_m1[j]; int bi = s_i1[j]; float b2 = s_m2[j];
    MY = fmaxf(MY, s_my[j]);
    if (b1 > M1)      { M2nd = fmaxf(M1, b2); M1 = b1; AM = bi; }
    else if (b1 < M1) { M2nd = fmaxf(M2nd, b1); }
    else              { AM = (bi < AM) ? bi : AM; M2nd = M1; }
  }

  if (M1 - M2nd < CAND_WIN) {
    const float thr = M1 - CAND_WIN;
#pragma unroll
    for (int i = 0; i < 32; ++i) {
      if (lv[i] >= thr) {
        int p = atomicAdd(&scount, 1);
        if (p < MAXCAND) cands[p] = t * 32 + i;
      }
    }
  }

  float z1 = 0.0f, z2 = 0.0f, ql = 0.0f;
#pragma unroll
  for (int i = 0; i < 32; ++i) {
    float e1 = __expf(lv[i] - M1);
    float e2 = __expf(yv[i] - MY);
    z1 += e1; z2 += e2; ql = fmaf(e1, lv[i], ql);
    yv[i] = e2;
  }
#pragma unroll
  for (int o = 16; o > 0; o >>= 1) {
    z1 += __shfl_xor_sync(0xFFFFFFFFu, z1, o);
    z2 += __shfl_xor_sync(0xFFFFFFFFu, z2, o);
    ql += __shfl_xor_sync(0xFFFFFFFFu, ql, o);
  }
  if (lane == 0) { s_z1[w] = z1; s_z2[w] = z2; s_ql[w] = ql; }
  __syncthreads();
  float Z1 = 0.0f, Z2 = 0.0f, QL = 0.0f;
#pragma unroll
  for (int j = 0; j < 8; ++j) { Z1 += s_z1[j]; Z2 += s_z2[j]; QL += s_ql[j]; }
  const float rZ2 = 1.0f / Z2;

  __half w16[32];
#pragma unroll
  for (int i = 0; i < 32; ++i) w16[i] = __float2half_rn(yv[i] * rZ2);
  {
    __half* wp = g_w16 + (size_t)row * NCODES + t * 32;
#pragma unroll
    for (int j = 0; j < 4; ++j) ((uint4*)wp)[j] = ((const uint4*)w16)[j];
  }
  if (t == 0) {
    float lZ1 = logf(Z1);
    g_kl[row] = QL / Z1 - M1 - lZ1 + 9.0109131f;   // ln(8192)=9.0109131
    out[CODES_OFF + row] = (float)AM;
    if (scount > 1) {
      int j = atomicAdd(&g_fixn, 1);
      g_fixrows[j] = row;
      int nc = (scount <= MAXCAND) ? scount : 0;
      g_fixnc[j] = nc;
      for (int q = 0; q < nc; ++q) g_fixcand[j][q] = cands[q];
    }
  }
}

// ---------------- exact fp32 rescore (candidates, fallback full) ------------
__global__ __launch_bounds__(256) void fixup_kernel(const float* __restrict__ z,
                                                    const float* __restrict__ cb,
                                                    float* __restrict__ out)
{
  __shared__ float zs[256];
  __shared__ float scr[MAXCAND];
  __shared__ float rv[256];
  __shared__ int   ri[256];
  const int t = threadIdx.x, w = t >> 5, lane = t & 31;
  const int nfix = g_fixn;

  for (int e = blockIdx.x; e < nfix; e += gridDim.x) {
    const int row = g_fixrows[e];
    const int nc  = g_fixnc[e];
    zs[t] = z[(size_t)row * DIM + t];
    __syncthreads();

    if (nc > 0) {
      if (w < nc) {
        int code = g_fixcand[e][w];
        const float* cp = cb + (size_t)code * DIM + lane * 8;
        float s = 0.0f;
#pragma unroll
        for (int u = 0; u < 8; ++u) s = fmaf(zs[lane * 8 + u], cp[u], s);
#pragma unroll
        for (int o = 16; o > 0; o >>= 1) s += __shfl_xor_sync(0xFFFFFFFFu, s, o);
        if (lane == 0) scr[w] = s;
      }
      __syncthreads();
      if (t == 0) {
        float best = -CUDART_INF_F; int bi = 0x7FFFFFFF;
        for (int ci = 0; ci < nc; ++ci) {
          int code = g_fixcand[e][ci];
          float s = scr[ci];
          if (s > best || (s == best && code < bi)) { best = s; bi = code; }
        }
        out[CODES_OFF + row] = (float)bi;
      }
    } else {
      float best = -CUDART_INF_F; int bi = 0;
      for (int c = t; c < NCODES; c += 256) {
        const float* cp = cb + (size_t)c * DIM;
        float s0 = 0.f, s1 = 0.f, s2 = 0.f, s3 = 0.f;
#pragma unroll 8
        for (int k = 0; k < DIM; k += 4) {
          s0 = fmaf(zs[k],     cp[k],     s0);
          s1 = fmaf(zs[k + 1], cp[k + 1], s1);
          s2 = fmaf(zs[k + 2], cp[k + 2], s2);
          s3 = fmaf(zs[k + 3], cp[k + 3], s3);
        }
        float s = (s0 + s1) + (s2 + s3);
        if (s > best) { best = s; bi = c; }
      }
      rv[t] = best; ri[t] = bi;
      __syncthreads();
      for (int s = 128; s > 0; s >>= 1) {
        if (t < s) {
          float v = rv[t + s]; int vi = ri[t + s];
          if (v > rv[t] || (v == rv[t] && vi < ri[t])) { rv[t] = v; ri[t] = vi; }
        }
        __syncthreads();
      }
      if (t == 0) out[CODES_OFF + row] = (float)ri[0];
    }
    __syncthreads();
  }
}

// ---------------- finalize losses ------------------------------------------
__global__ __launch_bounds__(256) void finalize_kernel(float* __restrict__ out)
{
  __shared__ double red[256];
  const int t = threadIdx.x;
  double cs = 0.0;
  for (int i = t; i < 4096; i += 256) cs += g_part[i];
  red[t] = cs;
  __syncthreads();
  for (int s = 128; s > 0; s >>= 1) { if (t < s) red[t] += red[t + s]; __syncthreads(); }
  const double commit_sum = red[0];
  __syncthreads();
  double ks = 0.0;
  for (int i = t; i < NROWS; i += 256) ks += (double)g_kl[i];
  red[t] = ks;
  __syncthreads();
  for (int s = 128; s > 0; s >>= 1) { if (t < s) red[t] += red[t + s]; __syncthreads(); }
  if (t == 0) {
    float commit = 0.25f * (float)(commit_sum / (double)ZQ_ELEMS);
    float klm    = 0.01f * (float)(red[0] / (double)NROWS);
    out[LOSS_OFF] = commit + klm;
  }
}

// ---------------- launch ----------------------------------------------------
extern "C" void kernel_launch(void* const* d_in, const int* in_sizes, int n_in,
                              void* d_out, int out_size)
{
  const float* z  = (const float*)d_in[0];
  const float* cb = (const float*)d_in[1];
  float* out = (float*)d_out;

  void *pl, *pw, *pz16, *pch, *pcl, *pcth, *pzqp;
  cudaGetSymbolAddress(&pl, g_logits);
  cudaGetSymbolAddress(&pw, g_w16);
  cudaGetSymbolAddress(&pz16, g_z16);
  cudaGetSymbolAddress(&pch, g_ch16);
  cudaGetSymbolAddress(&pcl, g_cl16);
  cudaGetSymbolAddress(&pcth, g_cth16);
  cudaGetSymbolAddress(&pzqp, g_zqp);

  cudaFuncSetAttribute(gemm_hmma_kernel<2>,
                       cudaFuncAttributeMaxDynamicSharedMemorySize, GEMM_SMEM);
  cudaFuncSetAttribute(gemm_hmma_kernel<1>,
                       cudaFuncAttributeMaxDynamicSharedMemorySize, GEMM_SMEM);

  conv_all_kernel<<<ZQ_ELEMS / 256, 256>>>(z, cb);      // 1

  // 2: GEMM1 logits = z16*ch16 + z16*cl16, fp16 2-phase, 128x128 tile
  dim3 g1(NCODES / 128, NROWS / 128, 1);
  gemm_hmma_kernel<2><<<g1, 256, GEMM_SMEM>>>(
      (const uint16_t*)pz16,
      (const uint16_t*)pch, (const uint16_t*)pcl,
      (float*)pl, NCODES, DIM, DIM, 0);

  pad_kernel<<<1, 32>>>();                              // 3

  row_kernel<<<NROWS, 256>>>(out);                      // 4 (ncu slot)

  // 5: GEMM2 split-K(4): zq_part[c] = w16 @ cth16 over K-chunk c
  dim3 g2(DIM / 128, NROWS / 128, SPLITK);
  gemm_hmma_kernel<1><<<g2, 256, GEMM_SMEM>>>(
      (const uint16_t*)pw,
      (const uint16_t*)pcth, (const uint16_t*)pcth,
      (float*)pzqp, DIM, KCHUNK, NCODES, (size_t)ZQ_ELEMS);

  zq_reduce_kernel<<<ZQ_ELEMS / 1024, 256>>>(z, out);   // 6
  fixup_kernel<<<128, 256>>>(z, cb, out);               // 7
  finalize_kernel<<<1, 256>>>(out);                     // 8
}